// round 1
// baseline (speedup 1.0000x reference)
#include <cuda_runtime.h>
#include <math.h>

// Problem constants (fixed by the dataset)
#define BATCH   2
#define NQ      16384
#define NATOMS  1024
#define KDIM    256
#define ODIM    256
#define NROWS   (BATCH * NQ)        // 32768
#define OMEGA0  30.0f
#define EPSD    1e-4f

// Scratch for per-row omega (allocation-free: __device__ global)
static __device__ float g_omega[NROWS];

// ---------------------------------------------------------------------------
// Kernel A: freq-net + min-distance -> omega per (b, n)
// One thread per query. Atoms for the batch cached in SMEM as float4.
// min over atoms done on squared distance (sqrt/max are monotone).
// ---------------------------------------------------------------------------
__global__ __launch_bounds__(256)
void omega_kernel(const float* __restrict__ q,
                  const float* __restrict__ atoms,
                  const float* __restrict__ fw1,
                  const float* __restrict__ fb1,
                  const float* __restrict__ fw2,
                  const float* __restrict__ fb2)
{
    __shared__ float4 sA[NATOMS];
    const int b   = blockIdx.y;
    const int tid = threadIdx.x;

    // Load this batch's atoms into SMEM (padded float4 for single LDS.128)
    const float* ab = atoms + (size_t)b * NATOMS * 3;
    for (int j = tid; j < NATOMS; j += blockDim.x) {
        sA[j] = make_float4(ab[3 * j], ab[3 * j + 1], ab[3 * j + 2], 0.0f);
    }
    __syncthreads();

    const int n = blockIdx.x * blockDim.x + tid;
    const size_t row = (size_t)b * NQ + n;

    const float qx = q[row * 3 + 0];
    const float qy = q[row * 3 + 1];
    const float qz = q[row * 3 + 2];

    // freq_net: Linear(3,16) -> softplus -> Linear(16,1)
    float ls = fb2[0];
#pragma unroll
    for (int j = 0; j < 16; ++j) {
        float z = fmaf(fw1[3 * j + 0], qx,
                  fmaf(fw1[3 * j + 1], qy,
                  fmaf(fw1[3 * j + 2], qz, fb1[j])));
        // numerically stable softplus: max(z,0) + log1p(exp(-|z|))
        float sp = fmaxf(z, 0.0f) + log1pf(expf(-fabsf(z)));
        ls = fmaf(fw2[j], sp, ls);
    }
    // clamp [0,5]; fmaxf(NaN,0)=0 also covers nan_to_num
    ls = fminf(fmaxf(ls, 0.0f), 5.0f);

    // min squared distance over atoms
    float md = 3.4e38f;
#pragma unroll 8
    for (int j = 0; j < NATOMS; ++j) {
        float4 a = sA[j];
        float dx = qx - a.x;
        float dy = qy - a.y;
        float dz = qz - a.z;
        float d2 = fmaf(dx, dx, fmaf(dy, dy, dz * dz));
        md = fminf(md, d2);
    }
    float mind = sqrtf(fmaxf(md, EPSD));

    g_omega[row] = OMEGA0 * (1.0f + ls * expf(-mind));
}

// ---------------------------------------------------------------------------
// Kernel B: SGEMM (32768x256 @ 256x256, both operands K-contiguous -> A*B^T)
// with fused epilogue out = sin(omega * (acc + bias)).
// Tiles: BM=128, BN=128, BK=16; 256 threads; 8x8 register micro-tile.
// ---------------------------------------------------------------------------
#define BM 128
#define BN 128
#define BK 16
#define TM 8
#define TN 8

__global__ __launch_bounds__(256, 2)
void siren_gemm_kernel(const float* __restrict__ X,
                       const float* __restrict__ W,
                       const float* __restrict__ bias,
                       float* __restrict__ out)
{
    __shared__ float As[BK][BM];
    __shared__ float Bs[BK][BN];

    const int tid  = threadIdx.x;
    const int bcol = blockIdx.x;   // 0..1   (ODIM / BN)
    const int brow = blockIdx.y;   // 0..255 (NROWS / BM)

    const float* Xt = X + (size_t)brow * BM * KDIM;
    const float* Wt = W + (size_t)bcol * BN * KDIM;

    const int tr = (tid / 16) * TM;   // row offset of this thread's micro-tile
    const int tc = (tid % 16) * TN;   // col offset

    float acc[TM][TN];
#pragma unroll
    for (int i = 0; i < TM; ++i)
#pragma unroll
        for (int j = 0; j < TN; ++j) acc[i][j] = 0.0f;

    for (int k0 = 0; k0 < KDIM; k0 += BK) {
        // Cooperative load: 128 rows x 16 k-cols from each operand,
        // stored transposed so the inner loop reads contiguous float4.
#pragma unroll
        for (int l = 0; l < 2; ++l) {
            int lin = tid + l * 256;
            int r   = lin >> 2;            // 0..127
            int c   = (lin & 3) * 4;       // 0,4,8,12
            float4 xv = *(const float4*)(Xt + (size_t)r * KDIM + k0 + c);
            As[c + 0][r] = xv.x; As[c + 1][r] = xv.y;
            As[c + 2][r] = xv.z; As[c + 3][r] = xv.w;
            float4 wv = *(const float4*)(Wt + (size_t)r * KDIM + k0 + c);
            Bs[c + 0][r] = wv.x; Bs[c + 1][r] = wv.y;
            Bs[c + 2][r] = wv.z; Bs[c + 3][r] = wv.w;
        }
        __syncthreads();

#pragma unroll
        for (int k = 0; k < BK; ++k) {
            float a[TM], bb[TN];
            *(float4*)&a[0]  = *(const float4*)&As[k][tr];
            *(float4*)&a[4]  = *(const float4*)&As[k][tr + 4];
            *(float4*)&bb[0] = *(const float4*)&Bs[k][tc];
            *(float4*)&bb[4] = *(const float4*)&Bs[k][tc + 4];
#pragma unroll
            for (int i = 0; i < TM; ++i)
#pragma unroll
                for (int j = 0; j < TN; ++j)
                    acc[i][j] = fmaf(a[i], bb[j], acc[i][j]);
        }
        __syncthreads();
    }

    // Fused epilogue: out = sin(omega[row] * (acc + bias[col]))
    float bv[TN];
#pragma unroll
    for (int j = 0; j < TN; ++j) bv[j] = bias[bcol * BN + tc + j];

#pragma unroll
    for (int i = 0; i < TM; ++i) {
        size_t row = (size_t)brow * BM + tr + i;
        float om = g_omega[row];
        float* o = out + row * ODIM + bcol * BN + tc;
        float res[TN];
#pragma unroll
        for (int j = 0; j < TN; ++j)
            res[j] = sinf(om * (acc[i][j] + bv[j]));
        *(float4*)&o[0] = *(const float4*)&res[0];
        *(float4*)&o[4] = *(const float4*)&res[4];
    }
}

// ---------------------------------------------------------------------------
// Launch
// ---------------------------------------------------------------------------
extern "C" void kernel_launch(void* const* d_in, const int* in_sizes, int n_in,
                              void* d_out, int out_size)
{
    const float* x     = (const float*)d_in[0];   // [B, N, 256]
    const float* q     = (const float*)d_in[1];   // [B, N, 3]
    const float* atoms = (const float*)d_in[2];   // [B, M, 3]
    const float* W     = (const float*)d_in[3];   // [256, 256]
    const float* bias  = (const float*)d_in[4];   // [256]
    const float* fw1   = (const float*)d_in[5];   // [16, 3]
    const float* fb1   = (const float*)d_in[6];   // [16]
    const float* fw2   = (const float*)d_in[7];   // [1, 16]
    const float* fb2   = (const float*)d_in[8];   // [1]
    float* out = (float*)d_out;                   // [B, N, 256] fp32

    (void)in_sizes; (void)n_in; (void)out_size;

    dim3 gA(NQ / 256, BATCH);
    omega_kernel<<<gA, 256>>>(q, atoms, fw1, fb1, fw2, fb2);

    dim3 gB(ODIM / BN, NROWS / BM);
    siren_gemm_kernel<<<gB, 256>>>(x, W, bias, out);
}

// round 3
// speedup vs baseline: 1.2859x; 1.2859x over previous
#include <cuda_runtime.h>
#include <cuda_bf16.h>
#include <stdint.h>
#include <math.h>

// ---------------------------------------------------------------- constants
#define BATCH   2
#define NQ      16384
#define NATOMS  1024
#define KDIM    256
#define ODIM    256
#define NROWS   (BATCH * NQ)     // 32768
#define OMEGA0  30.0f
#define EPSD    1e-4f

#define BM      128              // CTA rows
#define BN      256              // CTA cols (full ODIM)
#define BKC     32               // K per chunk
#define NCHUNK  (KDIM / BKC)     // 8

// SMEM stage layout (bytes). Rows padded to 40 bf16 (80 B) for conflict-free
// fragment loads (80 mod 128 covers all 32 banks across 8 rows).
#define ROWB    80
#define OFF_AH  0
#define OFF_AL  10240            // 128 * 80
#define OFF_BH  20480
#define OFF_BL  40960            // 256 * 80 after BH
#define STAGE   61440
#define EPI_STRIDE 264           // 256 + 8 words: stride mod 32 == 8 -> 2-wavefront STS.64
#define SM_BYTES 135168          // max(2*STAGE, 128*264*4)

static __device__ float          g_omega[NROWS];
static __device__ __nv_bfloat16  g_Whi[ODIM * KDIM];
static __device__ __nv_bfloat16  g_Wlo[ODIM * KDIM];

// ---------------------------------------------------------------- helpers
__device__ __forceinline__ uint32_t smem_u32(const void* p) {
    uint32_t a;
    asm("{ .reg .u64 t; cvta.to.shared.u64 t, %1; cvt.u32.u64 %0, t; }" : "=r"(a) : "l"(p));
    return a;
}
__device__ __forceinline__ uint32_t lds32(uint32_t a) {
    uint32_t v; asm volatile("ld.shared.b32 %0, [%1];" : "=r"(v) : "r"(a)); return v;
}
__device__ __forceinline__ void sts_u2(uint32_t a, uint32_t x, uint32_t y) {
    asm volatile("st.shared.v2.b32 [%0], {%1, %2};" :: "r"(a), "r"(x), "r"(y));
}
__device__ __forceinline__ void cp16(uint32_t dst, const void* src) {
    asm volatile("cp.async.cg.shared.global [%0], [%1], 16;" :: "r"(dst), "l"(src));
}
#define CP_COMMIT() asm volatile("cp.async.commit_group;")
#define CP_WAIT0()  asm volatile("cp.async.wait_group 0;")

__device__ __forceinline__ void mma_bf16(float* c, uint32_t a0, uint32_t a1,
                                         uint32_t a2, uint32_t a3,
                                         uint32_t b0, uint32_t b1) {
    asm volatile(
        "mma.sync.aligned.m16n8k16.row.col.f32.bf16.bf16.f32 "
        "{%0,%1,%2,%3}, {%4,%5,%6,%7}, {%8,%9}, {%0,%1,%2,%3};"
        : "+f"(c[0]), "+f"(c[1]), "+f"(c[2]), "+f"(c[3])
        : "r"(a0), "r"(a1), "r"(a2), "r"(a3), "r"(b0), "r"(b1));
}
__device__ __forceinline__ uint32_t pack_hi(float x, float y) {
    return (uint32_t)__bfloat16_as_ushort(__float2bfloat16(x)) |
           ((uint32_t)__bfloat16_as_ushort(__float2bfloat16(y)) << 16);
}
__device__ __forceinline__ uint32_t pack_lo(float x, float y) {
    float rx = x - __bfloat162float(__float2bfloat16(x));
    float ry = y - __bfloat162float(__float2bfloat16(y));
    return pack_hi(rx, ry);
}

// ---------------------------------------------------------------- kernel A: omega
__global__ __launch_bounds__(256)
void omega_kernel(const float* __restrict__ q, const float* __restrict__ atoms,
                  const float* __restrict__ fw1, const float* __restrict__ fb1,
                  const float* __restrict__ fw2, const float* __restrict__ fb2)
{
    __shared__ float4 sA[NATOMS];
    const int b = blockIdx.y, tid = threadIdx.x;
    const float* ab = atoms + (size_t)b * NATOMS * 3;
    for (int j = tid; j < NATOMS; j += blockDim.x)
        sA[j] = make_float4(ab[3*j], ab[3*j+1], ab[3*j+2], 0.0f);
    __syncthreads();

    const int n = blockIdx.x * blockDim.x + tid;
    const size_t row = (size_t)b * NQ + n;
    const float qx = q[row*3+0], qy = q[row*3+1], qz = q[row*3+2];

    float ls = fb2[0];
#pragma unroll
    for (int j = 0; j < 16; ++j) {
        float z = fmaf(fw1[3*j], qx, fmaf(fw1[3*j+1], qy, fmaf(fw1[3*j+2], qz, fb1[j])));
        float sp = fmaxf(z, 0.0f) + log1pf(expf(-fabsf(z)));
        ls = fmaf(fw2[j], sp, ls);
    }
    ls = fminf(fmaxf(ls, 0.0f), 5.0f);

    float md = 3.4e38f;
#pragma unroll 8
    for (int j = 0; j < NATOMS; ++j) {
        float4 a = sA[j];
        float dx = qx - a.x, dy = qy - a.y, dz = qz - a.z;
        md = fminf(md, fmaf(dx, dx, fmaf(dy, dy, dz*dz)));
    }
    float mind = sqrtf(fmaxf(md, EPSD));
    g_omega[row] = OMEGA0 * (1.0f + ls * expf(-mind));
}

// ---------------------------------------------------------------- W hi/lo split
__global__ __launch_bounds__(256)
void wsplit_kernel(const float* __restrict__ W)
{
    int i = blockIdx.x * 256 + threadIdx.x;
    float w = W[i];
    __nv_bfloat16 h = __float2bfloat16(w);
    g_Whi[i] = h;
    g_Wlo[i] = __float2bfloat16(w - __bfloat162float(h));
}

// ---------------------------------------------------------------- GEMM + sin epilogue
__global__ __launch_bounds__(256, 1)
void siren_mma_gemm(const float* __restrict__ X, const float* __restrict__ bias,
                    float* __restrict__ out)
{
    extern __shared__ char sb[];
    const uint32_t sbase = smem_u32(sb);

    const int tid   = threadIdx.x;
    const int wid   = tid >> 5;
    const int lane  = tid & 31;
    const int warpM = (wid & 1) * 64;   // 2 M-warps
    const int warpN = (wid >> 1) * 64;  // 4 N-warps
    const int gRow0 = blockIdx.x * BM;

    const int lr = lane >> 2;           // 0..7
    const int lc = (lane & 3) * 2;      // 0,2,4,6

    float acc[4][8][4];
#pragma unroll
    for (int i = 0; i < 4; ++i)
#pragma unroll
        for (int j = 0; j < 8; ++j)
#pragma unroll
            for (int k = 0; k < 4; ++k) acc[i][j][k] = 0.0f;

    // X loader indices: thread -> (row, k-half)
    const int xr = tid >> 1;            // 0..127
    const int xh = tid & 1;             // 0 / 1 (k 0-15 / 16-31)
    const float* Xrow = X + (size_t)(gRow0 + xr) * KDIM + xh * 16;

    // W cp.async indices: 4 x 16B per matrix per chunk
    // lin = tid + i*256 : n = lin>>2 (0..255), q = lin&3 (16B quarter of 64B row)
    // dst byte = n*80 + q*16 ; src = g_W?[n*256 + c*32 + q*8]

    // ---- prologue: load chunk 0 ----
    {
        float4 v0 = *(const float4*)(Xrow + 0);
        float4 v1 = *(const float4*)(Xrow + 4);
        float4 v2 = *(const float4*)(Xrow + 8);
        float4 v3 = *(const float4*)(Xrow + 12);
        uint32_t aBase = sbase + xr * ROWB + xh * 32;
        sts_u2(aBase + OFF_AH + 0,  pack_hi(v0.x, v0.y), pack_hi(v0.z, v0.w));
        sts_u2(aBase + OFF_AH + 8,  pack_hi(v1.x, v1.y), pack_hi(v1.z, v1.w));
        sts_u2(aBase + OFF_AH + 16, pack_hi(v2.x, v2.y), pack_hi(v2.z, v2.w));
        sts_u2(aBase + OFF_AH + 24, pack_hi(v3.x, v3.y), pack_hi(v3.z, v3.w));
        sts_u2(aBase + OFF_AL + 0,  pack_lo(v0.x, v0.y), pack_lo(v0.z, v0.w));
        sts_u2(aBase + OFF_AL + 8,  pack_lo(v1.x, v1.y), pack_lo(v1.z, v1.w));
        sts_u2(aBase + OFF_AL + 16, pack_lo(v2.x, v2.y), pack_lo(v2.z, v2.w));
        sts_u2(aBase + OFF_AL + 24, pack_lo(v3.x, v3.y), pack_lo(v3.z, v3.w));
#pragma unroll
        for (int i = 0; i < 4; ++i) {
            int lin = tid + i * 256;
            int n = lin >> 2, qd = lin & 3;
            uint32_t d = sbase + n * ROWB + qd * 16;
            cp16(d + OFF_BH, g_Whi + n * KDIM + qd * 8);
            cp16(d + OFF_BL, g_Wlo + n * KDIM + qd * 8);
        }
        CP_COMMIT();
        CP_WAIT0();
    }
    __syncthreads();

    // ---- main loop over 8 K-chunks, double-buffered ----
    int s = 0;
    for (int c = 0; c < NCHUNK; ++c) {
        float4 v0, v1, v2, v3;
        if (c + 1 < NCHUNK) {
            // next-chunk loads in flight during compute
            const float* Xn = Xrow + (c + 1) * BKC;
            v0 = *(const float4*)(Xn + 0);
            v1 = *(const float4*)(Xn + 4);
            v2 = *(const float4*)(Xn + 8);
            v3 = *(const float4*)(Xn + 12);
            uint32_t dstS = sbase + (s ^ 1) * STAGE;
#pragma unroll
            for (int i = 0; i < 4; ++i) {
                int lin = tid + i * 256;
                int n = lin >> 2, qd = lin & 3;
                uint32_t d = dstS + n * ROWB + qd * 16;
                const __nv_bfloat16* sh = g_Whi + n * KDIM + (c + 1) * BKC + qd * 8;
                const __nv_bfloat16* sl = g_Wlo + n * KDIM + (c + 1) * BKC + qd * 8;
                cp16(d + OFF_BH, sh);
                cp16(d + OFF_BL, sl);
            }
            CP_COMMIT();
        }

        // compute chunk c (2 ksteps of k16)
        const uint32_t st = sbase + s * STAGE;
#pragma unroll
        for (int ks = 0; ks < 2; ++ks) {
            const int kb = ks * 32 + lc * 2;   // byte offset of k pair
            uint32_t bh[8][2], bl[8][2];
#pragma unroll
            for (int nt = 0; nt < 8; ++nt) {
                uint32_t ba = st + (warpN + nt * 8 + lr) * ROWB + kb;
                bh[nt][0] = lds32(ba + OFF_BH);
                bh[nt][1] = lds32(ba + OFF_BH + 16);
                bl[nt][0] = lds32(ba + OFF_BL);
                bl[nt][1] = lds32(ba + OFF_BL + 16);
            }
#pragma unroll
            for (int mt = 0; mt < 4; ++mt) {
                uint32_t aa = st + (warpM + mt * 16 + lr) * ROWB + kb;
                uint32_t ah0 = lds32(aa + OFF_AH);
                uint32_t ah2 = lds32(aa + OFF_AH + 16);
                uint32_t ah1 = lds32(aa + OFF_AH + 640);
                uint32_t ah3 = lds32(aa + OFF_AH + 656);
                uint32_t al0 = lds32(aa + OFF_AL);
                uint32_t al2 = lds32(aa + OFF_AL + 16);
                uint32_t al1 = lds32(aa + OFF_AL + 640);
                uint32_t al3 = lds32(aa + OFF_AL + 656);
#pragma unroll
                for (int nt = 0; nt < 8; ++nt) {
                    mma_bf16(acc[mt][nt], ah0, ah1, ah2, ah3, bh[nt][0], bh[nt][1]);
                    mma_bf16(acc[mt][nt], ah0, ah1, ah2, ah3, bl[nt][0], bl[nt][1]);
                    mma_bf16(acc[mt][nt], al0, al1, al2, al3, bh[nt][0], bh[nt][1]);
                }
            }
        }

        if (c + 1 < NCHUNK) {
            uint32_t aBase = sbase + (s ^ 1) * STAGE + xr * ROWB + xh * 32;
            sts_u2(aBase + OFF_AH + 0,  pack_hi(v0.x, v0.y), pack_hi(v0.z, v0.w));
            sts_u2(aBase + OFF_AH + 8,  pack_hi(v1.x, v1.y), pack_hi(v1.z, v1.w));
            sts_u2(aBase + OFF_AH + 16, pack_hi(v2.x, v2.y), pack_hi(v2.z, v2.w));
            sts_u2(aBase + OFF_AH + 24, pack_hi(v3.x, v3.y), pack_hi(v3.z, v3.w));
            sts_u2(aBase + OFF_AL + 0,  pack_lo(v0.x, v0.y), pack_lo(v0.z, v0.w));
            sts_u2(aBase + OFF_AL + 8,  pack_lo(v1.x, v1.y), pack_lo(v1.z, v1.w));
            sts_u2(aBase + OFF_AL + 16, pack_lo(v2.x, v2.y), pack_lo(v2.z, v2.w));
            sts_u2(aBase + OFF_AL + 24, pack_lo(v3.x, v3.y), pack_lo(v3.z, v3.w));
            CP_WAIT0();
            __syncthreads();
            s ^= 1;
        }
    }
    __syncthreads();   // all reads of smem done; reuse for epilogue staging

    // ---- epilogue: sin(omega*(acc+bias)) -> SMEM stage -> coalesced STG ----
    float om[4][2];
#pragma unroll
    for (int mt = 0; mt < 4; ++mt) {
        om[mt][0] = g_omega[gRow0 + warpM + mt * 16 + lr];
        om[mt][1] = g_omega[gRow0 + warpM + mt * 16 + lr + 8];
    }
    float bv[8][2];
#pragma unroll
    for (int nt = 0; nt < 8; ++nt) {
        bv[nt][0] = __ldg(bias + warpN + nt * 8 + lc);
        bv[nt][1] = __ldg(bias + warpN + nt * 8 + lc + 1);
    }
    float* stg = (float*)sb;
#pragma unroll
    for (int mt = 0; mt < 4; ++mt) {
#pragma unroll
        for (int nt = 0; nt < 8; ++nt) {
            int r0 = warpM + mt * 16 + lr;
            int c0 = warpN + nt * 8 + lc;
            float x0 = sinf(om[mt][0] * (acc[mt][nt][0] + bv[nt][0]));
            float x1 = sinf(om[mt][0] * (acc[mt][nt][1] + bv[nt][1]));
            float x2 = sinf(om[mt][1] * (acc[mt][nt][2] + bv[nt][0]));
            float x3 = sinf(om[mt][1] * (acc[mt][nt][3] + bv[nt][1]));
            *(float2*)(stg + r0 * EPI_STRIDE + c0)       = make_float2(x0, x1);
            *(float2*)(stg + (r0 + 8) * EPI_STRIDE + c0) = make_float2(x2, x3);
        }
    }
    __syncthreads();
#pragma unroll
    for (int i = 0; i < 32; ++i) {
        int lin = tid + i * 256;        // float4 index over 128x256
        int r  = lin >> 6;
        int c4 = (lin & 63) * 4;
        float4 v = *(const float4*)(stg + r * EPI_STRIDE + c4);
        *(float4*)(out + (size_t)(gRow0 + r) * ODIM + c4) = v;
    }
}

// ---------------------------------------------------------------- launch
extern "C" void kernel_launch(void* const* d_in, const int* in_sizes, int n_in,
                              void* d_out, int out_size)
{
    const float* x     = (const float*)d_in[0];
    const float* q     = (const float*)d_in[1];
    const float* atoms = (const float*)d_in[2];
    const float* W     = (const float*)d_in[3];
    const float* bias  = (const float*)d_in[4];
    const float* fw1   = (const float*)d_in[5];
    const float* fb1   = (const float*)d_in[6];
    const float* fw2   = (const float*)d_in[7];
    const float* fb2   = (const float*)d_in[8];
    float* out = (float*)d_out;
    (void)in_sizes; (void)n_in; (void)out_size;

    cudaFuncSetAttribute(siren_mma_gemm, cudaFuncAttributeMaxDynamicSharedMemorySize, SM_BYTES);

    dim3 gA(NQ / 256, BATCH);
    omega_kernel<<<gA, 256>>>(q, atoms, fw1, fb1, fw2, fb2);
    wsplit_kernel<<<(ODIM * KDIM) / 256, 256>>>(W);
    siren_mma_gemm<<<NROWS / BM, 256, SM_BYTES>>>(x, bias, out);
}

// round 4
// speedup vs baseline: 1.9879x; 1.5459x over previous
#include <cuda_runtime.h>
#include <cuda_bf16.h>
#include <stdint.h>
#include <math.h>

// ---------------------------------------------------------------- constants
#define BATCH   2
#define NQ      16384
#define NATOMS  1024
#define KDIM    256
#define ODIM    256
#define NROWS   (BATCH * NQ)
#define OMEGA0  30.0f
#define EPSD    1e-4f

#define BM      128
#define BN      256
#define BKC     32
#define NCHUNK  (KDIM / BKC)     // 8

#define ROWB    80               // 40 bf16 per row (conflict-free pitch)
#define OFF_AH  0
#define OFF_AL  10240
#define OFF_BH  20480
#define OFF_BL  40960
#define STAGE   61440            // stages at 0 and 61440
#define OFF_ATOM  122880         // 1024 float4 = 16384 B
#define OFF_OMEGA 139264         // 128 floats
#define OFF_PART  139776         // 512 floats
#define SM_BYTES  141824
#define EPI_STRIDE 264           // epilogue staging pitch (floats)

static __device__ __nv_bfloat16 g_Whi[ODIM * KDIM];
static __device__ __nv_bfloat16 g_Wlo[ODIM * KDIM];
static __device__ float4        g_atom4[BATCH * NATOMS];

// ---------------------------------------------------------------- helpers
__device__ __forceinline__ uint32_t smem_u32(const void* p) {
    uint32_t a;
    asm("{ .reg .u64 t; cvta.to.shared.u64 t, %1; cvt.u32.u64 %0, t; }" : "=r"(a) : "l"(p));
    return a;
}
__device__ __forceinline__ void sts_u4(uint32_t a, uint32_t x, uint32_t y,
                                       uint32_t z, uint32_t w) {
    asm volatile("st.shared.v4.b32 [%0], {%1,%2,%3,%4};" :: "r"(a), "r"(x), "r"(y), "r"(z), "r"(w));
}
__device__ __forceinline__ void cp16(uint32_t dst, const void* src) {
    asm volatile("cp.async.cg.shared.global [%0], [%1], 16;" :: "r"(dst), "l"(src));
}
#define CP_COMMIT() asm volatile("cp.async.commit_group;")
#define CP_WAIT0()  asm volatile("cp.async.wait_group 0;")
#define CP_WAIT1()  asm volatile("cp.async.wait_group 1;")

#define LDSM4(r, a) \
    asm volatile("ldmatrix.sync.aligned.m8n8.x4.shared.b16 {%0,%1,%2,%3}, [%4];" \
        : "=r"((r)[0]), "=r"((r)[1]), "=r"((r)[2]), "=r"((r)[3]) : "r"(a))

__device__ __forceinline__ void mma_bf16(float* c, const uint32_t* a,
                                         uint32_t b0, uint32_t b1) {
    asm volatile(
        "mma.sync.aligned.m16n8k16.row.col.f32.bf16.bf16.f32 "
        "{%0,%1,%2,%3}, {%4,%5,%6,%7}, {%8,%9}, {%0,%1,%2,%3};"
        : "+f"(c[0]), "+f"(c[1]), "+f"(c[2]), "+f"(c[3])
        : "r"(a[0]), "r"(a[1]), "r"(a[2]), "r"(a[3]), "r"(b0), "r"(b1));
}
__device__ __forceinline__ void split2(float x, float y, uint32_t& h, uint32_t& l) {
    __nv_bfloat16 bx = __float2bfloat16(x), by = __float2bfloat16(y);
    h = (uint32_t)__bfloat16_as_ushort(bx) | ((uint32_t)__bfloat16_as_ushort(by) << 16);
    float rx = x - __bfloat162float(bx), ry = y - __bfloat162float(by);
    __nv_bfloat16 cx = __float2bfloat16(rx), cy = __float2bfloat16(ry);
    l = (uint32_t)__bfloat16_as_ushort(cx) | ((uint32_t)__bfloat16_as_ushort(cy) << 16);
}

// ---------------------------------------------------------------- prep: W split + atom pack
__global__ __launch_bounds__(256)
void prep_kernel(const float* __restrict__ W, const float* __restrict__ atoms)
{
    int b = blockIdx.x;
    if (b < (ODIM * KDIM) / 256) {
        int i = b * 256 + threadIdx.x;
        float w = W[i];
        __nv_bfloat16 h = __float2bfloat16(w);
        g_Whi[i] = h;
        g_Wlo[i] = __float2bfloat16(w - __bfloat162float(h));
    } else {
        int i = (b - (ODIM * KDIM) / 256) * 256 + threadIdx.x;  // 0..2047
        float ax = atoms[i*3], ay = atoms[i*3+1], az = atoms[i*3+2];
        g_atom4[i] = make_float4(ax, ay, az, fmaf(ax, ax, fmaf(ay, ay, az*az)));
    }
}

// ---------------------------------------------------------------- fused GEMM + omega + sin
__global__ __launch_bounds__(512, 1)
void siren_fused(const float* __restrict__ X, const float* __restrict__ Q,
                 const float* __restrict__ bias,
                 const float* __restrict__ fw1, const float* __restrict__ fb1,
                 const float* __restrict__ fw2, const float* __restrict__ fb2,
                 float* __restrict__ out)
{
    extern __shared__ char sb[];
    const uint32_t sbase = smem_u32(sb);

    const int tid  = threadIdx.x;
    const int lane = tid & 31;
    const int wid  = tid >> 5;
    const int gRow0 = blockIdx.x * BM;
    const int batch = (gRow0 >= NQ) ? 1 : 0;

    const int warpM = (wid & 3) * 32;
    const int warpN = (wid >> 2) * 64;
    const int lr = lane >> 2;
    const int lc = (lane & 3) * 2;
    const int l7 = lane & 7, g = lane >> 3;
    // ldmatrix per-lane in-tile offsets
    const uint32_t aoff = (uint32_t)((warpM + l7 + (g & 1) * 8) * ROWB + ((g >> 1) & 1) * 16);
    const uint32_t boff = (uint32_t)((warpN + l7 + (g >> 1) * 8) * ROWB + (g & 1) * 16);

    // ---- prologue async loads ----
    {   // atoms (pre-packed float4)
        const float4* ap = g_atom4 + batch * NATOMS;
#pragma unroll
        for (int i = 0; i < 2; ++i) {
            int lin = tid + i * 512;
            cp16(sbase + OFF_ATOM + lin * 16, ap + lin);
        }
    }
    CP_COMMIT();
#pragma unroll
    for (int i = 0; i < 2; ++i) {      // W chunk 0
        int lin = tid + i * 512;
        int n = lin >> 2, qd = lin & 3;
        uint32_t d = sbase + n * ROWB + qd * 16;
        cp16(d + OFF_BH, g_Whi + n * KDIM + qd * 8);
        cp16(d + OFF_BL, g_Wlo + n * KDIM + qd * 8);
    }
    CP_COMMIT();

    const int xr = tid >> 2, xq = tid & 3;
    const float* Xrow = X + (size_t)(gRow0 + xr) * KDIM + xq * 8;
    float4 v0 = *(const float4*)(Xrow);
    float4 v1 = *(const float4*)(Xrow + 4);

    CP_WAIT1();            // atoms landed
    __syncthreads();

    // ---- omega scan: query qi = tid&127, atom quarter qq = tid>>7 ----
    {
        const int qi = tid & 127, qq = tid >> 7;
        const float* qp = Q + (size_t)(gRow0 + qi) * 3;
        float qx = qp[0], qy = qp[1], qz = qp[2];
        float nqx = -2.f * qx, nqy = -2.f * qy, nqz = -2.f * qz;
        const float4* sAt = (const float4*)(sb + OFF_ATOM) + qq * 256;
        float md = 3.4e38f;
#pragma unroll 4
        for (int j = 0; j < 256; ++j) {
            float4 a = sAt[j];
            md = fminf(md, fmaf(a.x, nqx, fmaf(a.y, nqy, fmaf(a.z, nqz, a.w))));
        }
        ((float*)(sb + OFF_PART))[qq * 128 + qi] = md;
    }

    // ---- store X chunk 0 (hi/lo split) ----
    {
        uint32_t h0,h1,h2,h3,l0,l1,l2,l3;
        split2(v0.x, v0.y, h0, l0); split2(v0.z, v0.w, h1, l1);
        split2(v1.x, v1.y, h2, l2); split2(v1.z, v1.w, h3, l3);
        uint32_t aB = sbase + xr * ROWB + xq * 16;
        sts_u4(aB + OFF_AH, h0, h1, h2, h3);
        sts_u4(aB + OFF_AL, l0, l1, l2, l3);
    }
    CP_WAIT0();            // W chunk 0 landed
    __syncthreads();

    // ---- freq-net + omega (128 threads) ----
    if (tid < 128) {
        const float* part = (const float*)(sb + OFF_PART);
        float m = fminf(fminf(part[tid], part[128 + tid]),
                        fminf(part[256 + tid], part[384 + tid]));
        const float* qp = Q + (size_t)(gRow0 + tid) * 3;
        float qx = qp[0], qy = qp[1], qz = qp[2];
        float qsq = fmaf(qx, qx, fmaf(qy, qy, qz * qz));
        float mind = sqrtf(fmaxf(m + qsq, EPSD));
        float ls = fb2[0];
#pragma unroll
        for (int j = 0; j < 16; ++j) {
            float z = fmaf(fw1[3*j], qx, fmaf(fw1[3*j+1], qy, fmaf(fw1[3*j+2], qz, fb1[j])));
            float sp = fmaxf(z, 0.0f) + log1pf(expf(-fabsf(z)));
            ls = fmaf(fw2[j], sp, ls);
        }
        ls = fminf(fmaxf(ls, 0.0f), 5.0f);
        ((float*)(sb + OFF_OMEGA))[tid] = OMEGA0 * (1.0f + ls * expf(-mind));
    }

    // ---- accumulators ----
    float acc[2][8][4];
#pragma unroll
    for (int i = 0; i < 2; ++i)
#pragma unroll
        for (int j = 0; j < 8; ++j)
#pragma unroll
            for (int k = 0; k < 4; ++k) acc[i][j][k] = 0.0f;

    // ---- main loop: 8 K-chunks, double buffered ----
#pragma unroll 1
    for (int c = 0; c < NCHUNK; ++c) {
        const uint32_t st = sbase + (uint32_t)(c & 1) * STAGE;
        if (c + 1 < NCHUNK) {
            const float* Xn = Xrow + (c + 1) * BKC;
            float4 w0 = *(const float4*)(Xn);
            float4 w1 = *(const float4*)(Xn + 4);
            uint32_t dstS = sbase + (uint32_t)((c + 1) & 1) * STAGE;
            uint32_t h0,h1,h2,h3,l0,l1,l2,l3;
            split2(w0.x, w0.y, h0, l0); split2(w0.z, w0.w, h1, l1);
            split2(w1.x, w1.y, h2, l2); split2(w1.z, w1.w, h3, l3);
            uint32_t aB = dstS + xr * ROWB + xq * 16;
            sts_u4(aB + OFF_AH, h0, h1, h2, h3);
            sts_u4(aB + OFF_AL, l0, l1, l2, l3);
            const int ko = (c + 1) * BKC;
#pragma unroll
            for (int i = 0; i < 2; ++i) {
                int lin = tid + i * 512;
                int n = lin >> 2, qd = lin & 3;
                uint32_t d = dstS + n * ROWB + qd * 16;
                cp16(d + OFF_BH, g_Whi + n * KDIM + ko + qd * 8);
                cp16(d + OFF_BL, g_Wlo + n * KDIM + ko + qd * 8);
            }
            CP_COMMIT();
        }

#pragma unroll
        for (int ks = 0; ks < 2; ++ks) {
            uint32_t ah[2][4], al[2][4], bq[4][4];
            const uint32_t ab = st + aoff + ks * 32;
            LDSM4(ah[0], ab + OFF_AH);
            LDSM4(ah[1], ab + OFF_AH + 16 * ROWB);
            LDSM4(al[0], ab + OFF_AL);
            LDSM4(al[1], ab + OFF_AL + 16 * ROWB);
            const uint32_t bb = st + boff + ks * 32;
#pragma unroll
            for (int p = 0; p < 4; ++p) LDSM4(bq[p], bb + OFF_BH + p * 16 * ROWB);
#pragma unroll
            for (int mt = 0; mt < 2; ++mt)
#pragma unroll
                for (int p = 0; p < 4; ++p) {
                    mma_bf16(acc[mt][2*p],   ah[mt], bq[p][0], bq[p][1]);
                    mma_bf16(acc[mt][2*p+1], ah[mt], bq[p][2], bq[p][3]);
                    mma_bf16(acc[mt][2*p],   al[mt], bq[p][0], bq[p][1]);
                    mma_bf16(acc[mt][2*p+1], al[mt], bq[p][2], bq[p][3]);
                }
#pragma unroll
            for (int p = 0; p < 4; ++p) LDSM4(bq[p], bb + OFF_BL + p * 16 * ROWB);
#pragma unroll
            for (int mt = 0; mt < 2; ++mt)
#pragma unroll
                for (int p = 0; p < 4; ++p) {
                    mma_bf16(acc[mt][2*p],   ah[mt], bq[p][0], bq[p][1]);
                    mma_bf16(acc[mt][2*p+1], ah[mt], bq[p][2], bq[p][3]);
                }
        }
        CP_WAIT0();
        __syncthreads();
    }

    // ---- epilogue: sin(omega*(acc+bias)) via SMEM stage, coalesced STG ----
    float* stg = (float*)sb;
    const float* omg = (const float*)(sb + OFF_OMEGA);
#pragma unroll
    for (int mt = 0; mt < 2; ++mt) {
        int r0 = warpM + mt * 16 + lr;
        float o0 = omg[r0], o1 = omg[r0 + 8];
#pragma unroll
        for (int nt = 0; nt < 8; ++nt) {
            int c0 = warpN + nt * 8 + lc;
            float b0 = __ldg(bias + c0), b1 = __ldg(bias + c0 + 1);
            float* a = acc[mt][nt];
            *(float2*)(stg + r0 * EPI_STRIDE + c0) =
                make_float2(sinf(o0 * (a[0] + b0)), sinf(o0 * (a[1] + b1)));
            *(float2*)(stg + (r0 + 8) * EPI_STRIDE + c0) =
                make_float2(sinf(o1 * (a[2] + b0)), sinf(o1 * (a[3] + b1)));
        }
    }
    __syncthreads();
#pragma unroll
    for (int i = 0; i < 16; ++i) {
        int lin = tid + i * 512;
        int r = lin >> 6, c4 = (lin & 63) * 4;
        *(float4*)(out + (size_t)(gRow0 + r) * ODIM + c4) =
            *(const float4*)(stg + r * EPI_STRIDE + c4);
    }
}

// ---------------------------------------------------------------- launch
extern "C" void kernel_launch(void* const* d_in, const int* in_sizes, int n_in,
                              void* d_out, int out_size)
{
    const float* x     = (const float*)d_in[0];
    const float* q     = (const float*)d_in[1];
    const float* atoms = (const float*)d_in[2];
    const float* W     = (const float*)d_in[3];
    const float* bias  = (const float*)d_in[4];
    const float* fw1   = (const float*)d_in[5];
    const float* fb1   = (const float*)d_in[6];
    const float* fw2   = (const float*)d_in[7];
    const float* fb2   = (const float*)d_in[8];
    float* out = (float*)d_out;
    (void)in_sizes; (void)n_in; (void)out_size;

    cudaFuncSetAttribute(siren_fused, cudaFuncAttributeMaxDynamicSharedMemorySize, SM_BYTES);

    prep_kernel<<<(ODIM * KDIM) / 256 + (BATCH * NATOMS) / 256, 256>>>(W, atoms);
    siren_fused<<<NROWS / BM, 512, SM_BYTES>>>(x, q, bias, fw1, fb1, fw2, fb2, out);
}